// round 10
// baseline (speedup 1.0000x reference)
#include <cuda_runtime.h>
#include <math.h>
#include <stdint.h>

#define B 64
#define T 128
#define M 4
#define D 512
#define H 512
#define LNUM 2
#define K 6
#define F5H 2560   // 5*H

#define AST 36     // k_share A smem row stride
#define BST 136    // k_share B smem row stride
#define SMEM_S ((2*64*AST*2 + 2*32*BST*2) * 4)

// k_gemm: Af[4][32][9] float4 + Braw[4][16][136] float
#define SMEM_G (4*288*16 + 4*2176*4)

// ---------------- persistent scratch ----------------------------------------
__device__ float g_bufA[(size_t)T * B * 2 * D];
__device__ float g_bufB[(size_t)T * B * 2 * D];
__device__ float g_shareA[(size_t)T * B * H];
__device__ float g_shareB[(size_t)T * B * H];
// A rows pre-split & pair-packed: [row 128][pi 2048] = (hi(k),hi(k+4),lo(k),lo(k+4))
// pi = chunk*256 + s*8 + k8*4 + tig ; k = chunk*512 + s*16 + k8*8 + tig (+4)
__device__ float4 g_Apk[(size_t)128 * 2048];
__device__ float g_partial[(size_t)8 * 128 * F5H];
__device__ float g_cell[(size_t)B * 2 * H];
__device__ float g_shst[(size_t)B * H];
__device__ float g_cum[(size_t)B * H];
__device__ int   g_sel[B * 2 * 2];

__device__ __forceinline__ float to_tf32(float x) {
    float r; asm("cvt.rna.tf32.f32 %0, %1;" : "=f"(r) : "f"(x)); return r;
}
__device__ __forceinline__ void split2(float x, float& hi, float& lo) {
    hi = to_tf32(x);
    lo = to_tf32(x - hi);
}

__device__ __forceinline__ void mma8(float& c0, float& c1, float& c2, float& c3,
                                     uint32_t a0, uint32_t a1, uint32_t a2, uint32_t a3,
                                     uint32_t b0, uint32_t b1) {
    asm volatile("mma.sync.aligned.m16n8k8.row.col.f32.tf32.tf32.f32 "
                 "{%0,%1,%2,%3}, {%4,%5,%6,%7}, {%8,%9}, {%0,%1,%2,%3};"
                 : "+f"(c0), "+f"(c1), "+f"(c2), "+f"(c3)
                 : "r"(a0), "r"(a1), "r"(a2), "r"(a3), "r"(b0), "r"(b1));
}

__device__ __forceinline__ void cpa16(uint32_t dst, const void* src) {
    asm volatile("cp.async.cg.shared.global [%0], [%1], 16;" :: "r"(dst), "l"(src));
}
__device__ __forceinline__ void cpa_commit() {
    asm volatile("cp.async.commit_group;");
}

// ---------------- 3xtf32 share GEMM: [8192,2048]@[2048,512]+bias+relu --------
__global__ __launch_bounds__(256) void k_share(const float* __restrict__ feat,
                                               const float* __restrict__ W,
                                               const float* __restrict__ bias) {
    int col0 = blockIdx.x * 128;
    int row0 = blockIdx.y * 64;
    const float* Abase = feat + (size_t)row0 * 2048;

    extern __shared__ float sm[];
    float* Ah = sm;
    float* Al = Ah + 2 * 64 * AST;
    float* Bh = Al + 2 * 64 * AST;
    float* Bl = Bh + 2 * 32 * BST;

    int tid = threadIdx.x;
    int warp = tid >> 5, lane = tid & 31;
    int wm = warp >> 2, wn = warp & 3;
    int tg = lane >> 2, tig = lane & 3;
    int ar = tid >> 3, ac = (tid & 7) * 4;
    int br = warp, bc = lane * 4;

    float acc[2][4][4];
#pragma unroll
    for (int a = 0; a < 2; a++)
#pragma unroll
        for (int b = 0; b < 4; b++)
#pragma unroll
            for (int c = 0; c < 4; c++) acc[a][b][c] = 0.f;

    {
        float4 v0 = *(const float4*)&Abase[(size_t)ar * 2048 + ac];
        float4 v1 = *(const float4*)&Abase[(size_t)(ar + 32) * 2048 + ac];
        float h0, l0;
        float* pa = (float*)&v0;
#pragma unroll
        for (int q = 0; q < 4; q++) { split2(pa[q], h0, l0); Ah[(size_t)ar*AST + ac + q] = h0; Al[(size_t)ar*AST + ac + q] = l0; }
        pa = (float*)&v1;
#pragma unroll
        for (int q = 0; q < 4; q++) { split2(pa[q], h0, l0); Ah[(size_t)(ar+32)*AST + ac + q] = h0; Al[(size_t)(ar+32)*AST + ac + q] = l0; }
#pragma unroll
        for (int i = 0; i < 4; i++) {
            int kr = br + i * 8;
            float4 w = *(const float4*)&W[(size_t)kr * 512 + col0 + bc];
            float* pw = (float*)&w;
#pragma unroll
            for (int q = 0; q < 4; q++) { split2(pw[q], h0, l0); Bh[(size_t)kr*BST + bc + q] = h0; Bl[(size_t)kr*BST + bc + q] = l0; }
        }
    }
    __syncthreads();

    for (int kt = 0; kt < 64; kt++) {
        int cur = kt & 1;
        float4 pa0, pa1, pwv[4];
        if (kt < 63) {
            int k0 = (kt + 1) * 32;
            pa0 = *(const float4*)&Abase[(size_t)ar * 2048 + k0 + ac];
            pa1 = *(const float4*)&Abase[(size_t)(ar + 32) * 2048 + k0 + ac];
#pragma unroll
            for (int i = 0; i < 4; i++)
                pwv[i] = *(const float4*)&W[(size_t)(k0 + br + i * 8) * 512 + col0 + bc];
        }
        const float* Ach = Ah + cur * 64 * AST;
        const float* Acl = Al + cur * 64 * AST;
        const float* Bch = Bh + cur * 32 * BST;
        const float* Bcl = Bl + cur * 32 * BST;
#pragma unroll
        for (int k8 = 0; k8 < 4; k8++) {
            int kb = k8 * 8;
            uint32_t afh[2][4], afl[2][4];
#pragma unroll
            for (int mm = 0; mm < 2; mm++) {
                int r0 = wm * 32 + mm * 16;
                afh[mm][0] = __float_as_uint(Ach[(size_t)(r0 + tg) * AST + kb + tig]);
                afh[mm][1] = __float_as_uint(Ach[(size_t)(r0 + tg + 8) * AST + kb + tig]);
                afh[mm][2] = __float_as_uint(Ach[(size_t)(r0 + tg) * AST + kb + tig + 4]);
                afh[mm][3] = __float_as_uint(Ach[(size_t)(r0 + tg + 8) * AST + kb + tig + 4]);
                afl[mm][0] = __float_as_uint(Acl[(size_t)(r0 + tg) * AST + kb + tig]);
                afl[mm][1] = __float_as_uint(Acl[(size_t)(r0 + tg + 8) * AST + kb + tig]);
                afl[mm][2] = __float_as_uint(Acl[(size_t)(r0 + tg) * AST + kb + tig + 4]);
                afl[mm][3] = __float_as_uint(Acl[(size_t)(r0 + tg + 8) * AST + kb + tig + 4]);
            }
#pragma unroll
            for (int nn = 0; nn < 4; nn++) {
                int n = wn * 32 + nn * 8 + tg;
                uint32_t bh0 = __float_as_uint(Bch[(size_t)(kb + tig) * BST + n]);
                uint32_t bh1 = __float_as_uint(Bch[(size_t)(kb + tig + 4) * BST + n]);
                uint32_t bl0 = __float_as_uint(Bcl[(size_t)(kb + tig) * BST + n]);
                uint32_t bl1 = __float_as_uint(Bcl[(size_t)(kb + tig + 4) * BST + n]);
#pragma unroll
                for (int mm = 0; mm < 2; mm++) {
                    mma8(acc[mm][nn][0], acc[mm][nn][1], acc[mm][nn][2], acc[mm][nn][3],
                         afh[mm][0], afh[mm][1], afh[mm][2], afh[mm][3], bh0, bh1);
                    mma8(acc[mm][nn][0], acc[mm][nn][1], acc[mm][nn][2], acc[mm][nn][3],
                         afh[mm][0], afh[mm][1], afh[mm][2], afh[mm][3], bl0, bl1);
                    mma8(acc[mm][nn][0], acc[mm][nn][1], acc[mm][nn][2], acc[mm][nn][3],
                         afl[mm][0], afl[mm][1], afl[mm][2], afl[mm][3], bh0, bh1);
                }
            }
        }
        if (kt < 63) {
            int nb = cur ^ 1;
            float h0, l0;
            float* p = (float*)&pa0;
#pragma unroll
            for (int q = 0; q < 4; q++) { split2(p[q], h0, l0); Ah[((size_t)nb*64 + ar)*AST + ac + q] = h0; Al[((size_t)nb*64 + ar)*AST + ac + q] = l0; }
            p = (float*)&pa1;
#pragma unroll
            for (int q = 0; q < 4; q++) { split2(p[q], h0, l0); Ah[((size_t)nb*64 + ar + 32)*AST + ac + q] = h0; Al[((size_t)nb*64 + ar + 32)*AST + ac + q] = l0; }
#pragma unroll
            for (int i = 0; i < 4; i++) {
                p = (float*)&pwv[i];
                int kr = nb * 32 + br + i * 8;
#pragma unroll
                for (int q = 0; q < 4; q++) { split2(p[q], h0, l0); Bh[(size_t)kr*BST + bc + q] = h0; Bl[(size_t)kr*BST + bc + q] = l0; }
            }
            __syncthreads();
        }
    }

#pragma unroll
    for (int mm = 0; mm < 2; mm++)
#pragma unroll
        for (int nn = 0; nn < 4; nn++) {
            int r = row0 + wm * 32 + mm * 16 + tg;
            int c = col0 + wn * 32 + nn * 8 + tig * 2;
#pragma unroll
            for (int h = 0; h < 2; h++) {
                int rr = r + h * 8;
                int bb = rr >> 7, tt = rr & 127;
                float v0 = acc[mm][nn][h * 2 + 0] + bias[c];
                float v1 = acc[mm][nn][h * 2 + 1] + bias[c + 1];
                v0 = v0 > 0.f ? v0 : 0.f;
                v1 = v1 > 0.f ? v1 : 0.f;
                *(float2*)&g_shareA[((size_t)tt * B + bb) * H + c] = make_float2(v0, v1);
            }
        }
}

// ---------------- group separation -> g_bufA [t][b][j][d] --------------------
__global__ __launch_bounds__(128) void k_groupsep(const float* __restrict__ feat,
                                                  const float* __restrict__ sepW,
                                                  const float* __restrict__ sepb) {
    int bt = blockIdx.x;          // b*T + t
    int b = bt >> 7, t = bt & 127;
    const float* fb = feat + (size_t)bt * (M * D);
    __shared__ float s_lg[M];
    int tid = threadIdx.x;
    int w = tid >> 5, lane = tid & 31;
    if (w < M) {
        float s = 0.f;
        for (int d = lane; d < D; d += 32) s += fb[w * D + d] * sepW[d];
#pragma unroll
        for (int o = 16; o; o >>= 1) s += __shfl_down_sync(0xffffffffu, s, o);
        if (lane == 0) s_lg[w] = s + sepb[0];
    }
    __syncthreads();
    float lg[M], mx = -1e30f;
#pragma unroll
    for (int m = 0; m < M; m++) { lg[m] = s_lg[m]; mx = fmaxf(mx, lg[m]); }
    float e[M], sum = 0.f;
#pragma unroll
    for (int m = 0; m < M; m++) { e[m] = expf(lg[m] - mx); sum += e[m]; }
    float sw[M], cnt0 = 0.f;
#pragma unroll
    for (int m = 0; m < M; m++) { sw[m] = (e[m] > 0.25f * sum) ? 1.f : 0.f; cnt0 += sw[m]; }
    float cnt1 = (float)M - cnt0;
    float inv0 = 1.f / (cnt0 + 1e-8f), inv1 = 1.f / (cnt1 + 1e-8f);
    float* o0 = g_bufA + ((size_t)t * B + b) * 2 * D;
    float* o1 = o0 + D;
    for (int d = tid; d < D; d += 128) {
        float s0 = 0.f, s1 = 0.f;
#pragma unroll
        for (int m = 0; m < M; m++) {
            float v = fb[m * D + d];
            s0 += sw[m] * v;
            s1 += (1.f - sw[m]) * v;
        }
        o0[d] = s0 * inv0;
        o1[d] = s1 * inv1;
    }
}

// ---------------- fused: finalize(t-1) + prep(t); one block per b ------------
__global__ __launch_bounds__(512) void k_step(const float* __restrict__ ctx,
                                              const float* __restrict__ archW,
                                              const float* __restrict__ archb,
                                              const float* __restrict__ bxp,
                                              const float* __restrict__ bhp,
                                              const float* __restrict__ bcp,
                                              int l, int t) {
    int b = blockIdx.x;
    int tid = threadIdx.x;
    const float* seq = l ? g_bufB : g_bufA;
    float* hid = l ? g_bufA : g_bufB;
    const float* shin = l ? g_shareB : g_shareA;
    float* shout = l ? g_shareA : g_shareB;

    __shared__ float s_h1[2][D];
    __shared__ float s_lg[2][K];
    __shared__ int s_sel[4];

    if (t == 0) {
        for (int i = tid; i < 2 * H; i += 512) g_cell[(size_t)b * 2 * H + i] = 0.f;
        for (int i = tid; i < H; i += 512) { g_shst[(size_t)b * H + i] = 0.f; g_cum[(size_t)b * H + i] = 0.f; }
        s_h1[0][tid] = 0.f;
        s_h1[1][tid] = 0.f;
    } else {
        int tp = t - 1;
        int p = tid;
        float sgsum = 0.f;
#pragma unroll
        for (int j = 0; j < 2; j++) {
            int k0 = g_sel[(b * 2 + j) * 2], k1 = g_sel[(b * 2 + j) * 2 + 1];
            float tot[5];
#pragma unroll
            for (int c = 0; c < 5; c++) {
                int f = c * 512 + p;
                size_t base = (size_t)(j * 64 + b) * F5H + f;
                float v = g_partial[base]
                        + g_partial[(size_t)1 * 128 * F5H + base]
                        + 0.5f * (g_partial[(size_t)(2 + k0) * 128 * F5H + base]
                                + g_partial[(size_t)(2 + k1) * 128 * F5H + base]);
                v += bxp[(size_t)(l * 2 + j) * F5H + f] + bhp[(size_t)(l * 2 + j) * F5H + f];
                v += 0.5f * (bcp[((size_t)(l * 2 + j) * K + k0) * F5H + f]
                           + bcp[((size_t)(l * 2 + j) * K + k1) * F5H + f]);
                tot[c] = v;
            }
            float ig = tot[0], fg = tot[1], og = tot[2], sg = tot[3], cc = tot[4];
            size_t ci = ((size_t)b * 2 + j) * H + p;
            float cell = g_cell[ci];
            float sf = 1.f / (1.f + expf(-fg));
            float si = 1.f / (1.f + expf(-ig));
            cell = (1.f - sf) * cell + si * tanhf(cc);
            g_cell[ci] = cell;
            float hv = (1.f / (1.f + expf(-og))) * tanhf(cell);
            hid[((size_t)tp * B + b) * 2 * H + (size_t)j * H + p] = hv;
            s_h1[j][p] = hv;
            sgsum += sg;
        }
        float gate = 1.f / (1.f + expf(-sgsum));
        size_t si = (size_t)b * H + p;
        float shf = shin[((size_t)tp * B + b) * H + p];
        float st = g_shst[si] + gate * shf;
        float cum = g_cum[si] + gate;
        g_shst[si] = st;
        g_cum[si] = cum;
        shout[((size_t)tp * B + b) * H + p] = st / cum;
    }
    if (t >= T) return;
    __syncthreads();

    int w = tid >> 5, lane = tid & 31;
    if (w < 12) {
        int j = w / K, k = w % K;
        const float* aW = archW + (size_t)l * H * K;
        float s = 0.f;
        for (int d = lane; d < D; d += 32) s += s_h1[j][d] * aW[(size_t)d * K + k];
#pragma unroll
        for (int o = 16; o; o >>= 1) s += __shfl_down_sync(0xffffffffu, s, o);
        if (lane == 0) s_lg[j][k] = s + archb[l * K + k];
    }
    __syncthreads();
    if (tid < 2) {
        int j = tid;
        int k0 = 0; float best = s_lg[j][0];
        for (int k = 1; k < K; k++) if (s_lg[j][k] > best) { best = s_lg[j][k]; k0 = k; }
        int k1 = -1; float b2 = 0.f;
        for (int k = 0; k < K; k++) {
            if (k == k0) continue;
            if (k1 < 0 || s_lg[j][k] > b2) { b2 = s_lg[j][k]; k1 = k; }
        }
        s_sel[j * 2] = k0; s_sel[j * 2 + 1] = k1;
        g_sel[(b * 2 + j) * 2] = k0;
        g_sel[(b * 2 + j) * 2 + 1] = k1;
    }

    const float* seq_t  = seq + ((size_t)t * B + b) * 2 * D;
    const float* seq_n  = (t + 1 < T) ? seq + ((size_t)(t + 1) * B + b) * 2 * D : 0;
    const float* h_prev2 = (t >= 2) ? hid + ((size_t)(t - 2) * B + b) * 2 * D : 0;
    const float* sc = ctx + ((size_t)b * T + t) * H;

    // unmasked concat row, split + pair-packed:
    // pi = chunk*256 + s*8 + k8*4 + tig -> k = chunk*512 + s*16 + k8*8 + tig (+4)
    for (int idx = tid; idx < 2 * 2048; idx += 512) {
        int j = idx >> 11;
        int pi = idx & 2047;
        int c = pi >> 8;
        int r = pi & 255;
        int s = r >> 3, q = r & 7;
        int kin = s * 16 + (q >> 2) * 8 + (q & 3);
        float vv[2];
#pragma unroll
        for (int hh = 0; hh < 2; hh++) {
            int d = kin + hh * 4;
            float v;
            if (c == 0) v = seq_t[j * D + d];
            else if (c == 1) v = s_h1[j][d];
            else {
                int k = c - 2;
                if (k == 0)      v = h_prev2 ? h_prev2[j * D + d] : 0.f;
                else if (k == 1) v = seq_n ? seq_n[j * D + d] : 0.f;
                else if (k == 2) v = s_h1[1 - j][d];
                else if (k == 3) v = seq_t[(1 - j) * D + d];
                else if (k == 4) v = seq_n ? seq_n[(1 - j) * D + d] : 0.f;
                else             v = sc[d];
            }
            vv[hh] = v;
        }
        float h0, l0, h4, l4;
        split2(vv[0], h0, l0);
        split2(vv[1], h4, l4);
        g_Apk[(size_t)(j * 64 + b) * 2048 + pi] = make_float4(h0, h4, l0, l4);
    }
}

// ---------------- per-step 3xtf32 GEMM: cp.async 4-stage pipeline ------------
// grid (20 cols, 2 j, 16 z): z<4 fixed chunks, z>=4 candidate gather.
// block 32 rows x 128 cols, 32 stages of 16 K, warp tile 16x32 (wm 2 x wn 4).
__global__ __launch_bounds__(256, 4) void k_gemm(const float* __restrict__ Wx,
                                                 const float* __restrict__ Wh,
                                                 const float* __restrict__ Wc,
                                                 int l) {
    int col0 = blockIdx.x * 128;
    int j = blockIdx.y;
    int z = blockIdx.z;
    int tid = threadIdx.x;
    int warp = tid >> 5, lane = tid & 31;

    __shared__ int s_list[32];
    __shared__ int s_cnt;
    __shared__ unsigned s_mask[2];

    int ks, tile;
    if (z < 4) { ks = z >> 1; tile = z & 1; }
    else       { ks = 2 + ((z - 4) >> 1); tile = (z - 4) & 1; }

    if (z < 4) {
        if (tid < 32) s_list[tid] = tile * 32 + tid;
        if (tid == 0) s_cnt = 64;
    } else {
        int k = ks - 2;
        if (tid < 32) s_list[tid] = -1;
        if (warp < 2) {
            int b = warp * 32 + lane;
            int s0 = g_sel[(b * 2 + j) * 2];
            int s1 = g_sel[(b * 2 + j) * 2 + 1];
            bool f = (s0 == k) || (s1 == k);
            unsigned m = __ballot_sync(0xffffffffu, f);
            if (lane == 0) s_mask[warp] = m;
        }
        __syncthreads();
        unsigned m0 = s_mask[0], m1 = s_mask[1];
        if (tid == 0) s_cnt = __popc(m0) + __popc(m1);
        if (warp < 2) {
            unsigned m = warp ? m1 : m0;
            if ((m >> lane) & 1u) {
                int pos = (warp ? __popc(m0) : 0) + __popc(m & ((1u << lane) - 1u));
                int p = pos - tile * 32;
                if (p >= 0 && p < 32) s_list[p] = warp * 32 + lane;
            }
        }
    }
    __syncthreads();
    if (tile * 32 >= s_cnt) return;

    const float* Wb;
    if (ks == 0)      Wb = Wx + (size_t)(l * 2 + j) * D * F5H;
    else if (ks == 1) Wb = Wh + (size_t)(l * 2 + j) * H * F5H;
    else              Wb = Wc + ((size_t)(l * 2 + j) * K + (ks - 2)) * (size_t)D * F5H;

    extern __shared__ char smraw[];
    float4* Af = (float4*)smraw;                    // [4][32][9]
    float*  Bfr = (float*)(smraw + 4 * 288 * 16);   // [4][16][136]
    uint32_t af_s = (uint32_t)__cvta_generic_to_shared(Af);
    uint32_t bf_s = (uint32_t)__cvta_generic_to_shared(Bfr);

    int wm = warp >> 2, wn = warp & 3;
    int tg = lane >> 2, tig = lane & 3;

    // copy roles
    int a_row = tid >> 3, a_q = tid & 7;            // A: one float4 per thread
    int b_r = tid >> 4, b_n8 = (tid & 15) * 8;      // B: two float4 per thread
    int myrow = s_list[a_row]; if (myrow < 0) myrow = 0;
    const float4* Apk = g_Apk + (size_t)j * 64 * 2048 + ks * 256;
    const float4* a_src = Apk + (size_t)myrow * 2048 + a_q;
    const float* b_src = Wb + (size_t)b_r * F5H + col0 + b_n8;
    uint32_t a_dst = af_s + (a_row * 9 + a_q) * 16;
    uint32_t b_dst = bf_s + (b_r * 136 + b_n8) * 4;

#define ISSUE_STAGE(s) do { \
        int _buf = (s) & 3; \
        cpa16(a_dst + _buf * 288 * 16, a_src + (s) * 8); \
        const float* _bs = b_src + (size_t)(s) * 16 * F5H; \
        uint32_t _bd = b_dst + _buf * 2176 * 4; \
        cpa16(_bd, _bs); \
        cpa16(_bd + 16, _bs + 4); \
        cpa_commit(); \
    } while (0)

    float acc[4][4];
#pragma unroll
    for (int a = 0; a < 4; a++)
#pragma unroll
        for (int c = 0; c < 4; c++) acc[a][c] = 0.f;

    ISSUE_STAGE(0);
    ISSUE_STAGE(1);
    ISSUE_STAGE(2);

    for (int kt = 0; kt < 32; kt++) {
        if (kt + 3 < 32) ISSUE_STAGE(kt + 3);
        if (kt <= 28)      asm volatile("cp.async.wait_group 3;");
        else if (kt == 29) asm volatile("cp.async.wait_group 2;");
        else if (kt == 30) asm volatile("cp.async.wait_group 1;");
        else               asm volatile("cp.async.wait_group 0;");
        __syncthreads();

        int buf = kt & 3;
        const float4* Ac = Af + buf * 288;
        const float* Bc = Bfr + buf * 2176;
#pragma unroll
        for (int k8 = 0; k8 < 2; k8++) {
            float4 f1 = Ac[(wm * 16 + tg) * 9 + k8 * 4 + tig];
            float4 f2 = Ac[(wm * 16 + tg + 8) * 9 + k8 * 4 + tig];
            uint32_t ah0 = __float_as_uint(f1.x), ah1 = __float_as_uint(f2.x);
            uint32_t ah2 = __float_as_uint(f1.y), ah3 = __float_as_uint(f2.y);
            uint32_t al0 = __float_as_uint(f1.z), al1 = __float_as_uint(f2.z);
            uint32_t al2 = __float_as_uint(f1.w), al3 = __float_as_uint(f2.w);
#pragma unroll
            for (int nn = 0; nn < 4; nn++) {
                int n = wn * 32 + nn * 8 + tg;
                float b0 = Bc[(k8 * 8 + tig) * 136 + n];
                float b1 = Bc[(k8 * 8 + tig + 4) * 136 + n];
                float bh0f, bl0f, bh1f, bl1f;
                split2(b0, bh0f, bl0f);
                split2(b1, bh1f, bl1f);
                uint32_t bh0 = __float_as_uint(bh0f), bh1 = __float_as_uint(bh1f);
                uint32_t bl0 = __float_as_uint(bl0f), bl1 = __float_as_uint(bl1f);
                mma8(acc[nn][0], acc[nn][1], acc[nn][2], acc[nn][3],
                     ah0, ah1, ah2, ah3, bh0, bh1);
                mma8(acc[nn][0], acc[nn][1], acc[nn][2], acc[nn][3],
                     ah0, ah1, ah2, ah3, bl0, bl1);
                mma8(acc[nn][0], acc[nn][1], acc[nn][2], acc[nn][3],
                     al0, al1, al2, al3, bh0, bh1);
            }
        }
        __syncthreads();
    }
#undef ISSUE_STAGE

    float* outp = g_partial + (size_t)ks * 128 * F5H;
    int rlo = s_list[wm * 16 + tg];
    int rhi = s_list[wm * 16 + tg + 8];
#pragma unroll
    for (int nn = 0; nn < 4; nn++) {
        int c = col0 + wn * 32 + nn * 8 + tig * 2;
        if (rlo >= 0)
            *(float2*)&outp[(size_t)(j * 64 + rlo) * F5H + c] = make_float2(acc[nn][0], acc[nn][1]);
        if (rhi >= 0)
            *(float2*)&outp[(size_t)(j * 64 + rhi) * F5H + c] = make_float2(acc[nn][2], acc[nn][3]);
    }
}

// ---------------- output assembly -------------------------------------------
__global__ void k_output(float* __restrict__ out) {
    size_t i = (size_t)blockIdx.x * 256 + threadIdx.x;
    size_t total = (size_t)B * T * 1536;
    if (i >= total) return;
    int c = (int)(i % 1536);
    size_t bt = i / 1536;
    int b = (int)(bt >> 7), t = (int)(bt & 127);
    float v;
    if (c < 1024) {
        size_t idx = ((size_t)t * B + b) * 1024 + c;
        v = 0.5f * (g_bufB[idx] + g_bufA[idx]);
    } else {
        int p = c - 1024;
        size_t idx = ((size_t)t * B + b) * H + p;
        v = 0.5f * (g_shareB[idx] + g_shareA[idx]);
    }
    out[i] = v;
}

// ---------------- launch ------------------------------------------------------
extern "C" void kernel_launch(void* const* d_in, const int* in_sizes, int n_in,
                              void* d_out, int out_size) {
    const float* feat = (const float*)d_in[0];
    const float* ctx  = (const float*)d_in[1];
    const float* l2sW = (const float*)d_in[2];
    const float* l2sb = (const float*)d_in[3];
    const float* sepW = (const float*)d_in[4];
    const float* sepb = (const float*)d_in[5];
    const float* aW   = (const float*)d_in[6];
    const float* ab   = (const float*)d_in[7];
    const float* Wx   = (const float*)d_in[8];
    const float* bx   = (const float*)d_in[9];
    const float* Wh   = (const float*)d_in[10];
    const float* bh   = (const float*)d_in[11];
    const float* Wc   = (const float*)d_in[12];
    const float* bc   = (const float*)d_in[13];
    float* out = (float*)d_out;

    cudaFuncSetAttribute(k_share, cudaFuncAttributeMaxDynamicSharedMemorySize, SMEM_S);
    cudaFuncSetAttribute(k_gemm, cudaFuncAttributeMaxDynamicSharedMemorySize, SMEM_G);

    k_share<<<dim3(4, 128), 256, SMEM_S>>>(feat, l2sW, l2sb);
    k_groupsep<<<B * T, 128>>>(feat, sepW, sepb);
    for (int l = 0; l < LNUM; l++) {
        for (int t = 0; t < T; t++) {
            k_step<<<B, 512>>>(ctx, aW, ab, bx, bh, bc, l, t);
            k_gemm<<<dim3(20, 2, 16), 256, SMEM_G>>>(Wx, Wh, Wc, l);
        }
        k_step<<<B, 512>>>(ctx, aW, ab, bx, bh, bc, l, T);
    }
    k_output<<<(int)(((size_t)B * T * 1536 + 255) / 256), 256>>>(out);
}